// round 11
// baseline (speedup 1.0000x reference)
#include <cuda_runtime.h>
#include <cstdint>

// VoxelHashTable: 2-level hash-grid trilinear interpolation.
// Inputs (metadata order):
//   d_in[0] query_pts (M,3) f32
//   d_in[1] feats0    (n0,32) f32
//   d_in[2] feats1    (n1,32) f32
//   d_in[3] h2v0      (2^20) i32
//   d_in[4] h2v1      (2^20) i32
// Output: (M, 64) f32  — [level0 32 | level1 32]
//
// Persistent grid-stride kernel: each warp processes many query PAIRS.
// Per-pair lane layout:
//   half  = lane>>4        which query of the pair
//   level = (lane>>3)&1    resolution level this lane serves
//   s     = lane&7         channel chunk (floats 4s..4s+3)
// Software pipeline (depth 1): while gathering pair i, the warp loads the
// query point and issues the scattered hash LDG for pair i+stride, so the
// ~600cyc hash latency is hidden under the previous gather on every
// iteration. Gathers are sequential per pair (the form ptxas pipelines best —
// the manually interleaved variant regressed by inflating live ranges).
// __launch_bounds__(256, 6): 40-reg budget ((256,7) truncates to 32 + spills).

#define TSIZE_MASK ((1 << 20) - 1)

// PRIMES % 2^20 (exact):
#define PMX 455773
#define PMY 475301
#define PMZ 655287

__global__ __launch_bounds__(256, 6) void voxel_hash_kernel(
    const float* __restrict__ q,
    const float* __restrict__ f0,
    const float* __restrict__ f1,
    const int* __restrict__ h0,
    const int* __restrict__ h1,
    float* __restrict__ out,
    int M)
{
    const int lane  = threadIdx.x & 31;
    const int gwarp = (blockIdx.x * blockDim.x + threadIdx.x) >> 5;
    const int nwarp = (gridDim.x * blockDim.x) >> 5;

    const int level = (lane >> 3) & 1;
    const int s     = lane & 7;
    const int half  = lane >> 4;

    const int npairs = (M + 1) / 2;

    const float res = level ? 0.24f : 0.12f;   // 0.24f == float32(0.12*2.0)
    const int*   __restrict__ hp = level ? h1 : h0;
    const float* __restrict__ fp = (level ? f1 : f0) + s * 4;
    const int src_base = lane & 0x18;          // (half<<4) | (level<<3)
    const int oxb = (lane >> 2) & 1;
    const int oyb = (lane >> 1) & 1;
    const int ozb = lane & 1;

    int p = gwarp;
    if (p >= npairs) return;

    // ---- Prologue for the first pair ----
    int qi = p * 2 + half;
    if (qi >= M) qi = M - 1;
    float fx, fy, fz;
    int vidx;
    {
        const float px = __ldg(q + qi * 3 + 0);
        const float py = __ldg(q + qi * 3 + 1);
        const float pz = __ldg(q + qi * 3 + 2);
        const float sx = __fdiv_rn(px, res);
        const float sy = __fdiv_rn(py, res);
        const float sz = __fdiv_rn(pz, res);
        const float bx = floorf(sx), by = floorf(sy), bz = floorf(sz);
        fx = sx - bx; fy = sy - by; fz = sz - bz;
        const unsigned hv = ((unsigned)(((int)bx + oxb) * PMX +
                                        ((int)by + oyb) * PMY +
                                        ((int)bz + ozb) * PMZ)) & TSIZE_MASK;
        vidx = __ldg(hp + hv);
    }

    for (;;) {
        const int pn = p + nwarp;
        const bool has_next = pn < npairs;

        // ---- Prefetch next pair: query load + hash LDG issued BEFORE the
        //      current gather, so their latency hides under it. ----
        int qin = qi;
        float fxn = 0.f, fyn = 0.f, fzn = 0.f;
        int vidxn = -1;
        if (has_next) {
            qin = pn * 2 + half;
            if (qin >= M) qin = M - 1;
            const float px = __ldg(q + qin * 3 + 0);
            const float py = __ldg(q + qin * 3 + 1);
            const float pz = __ldg(q + qin * 3 + 2);
            const float sx = __fdiv_rn(px, res);
            const float sy = __fdiv_rn(py, res);
            const float sz = __fdiv_rn(pz, res);
            const float bx = floorf(sx), by = floorf(sy), bz = floorf(sz);
            fxn = sx - bx; fyn = sy - by; fzn = sz - bz;
            const unsigned hv = ((unsigned)(((int)bx + oxb) * PMX +
                                            ((int)by + oyb) * PMY +
                                            ((int)bz + ozb) * PMZ)) & TSIZE_MASK;
            vidxn = __ldg(hp + hv);
        }

        // ---- Gather current pair ----
        {
            const float gx = 1.0f - fx, gy = 1.0f - fy, gz = 1.0f - fz;
            float4 acc = make_float4(0.f, 0.f, 0.f, 0.f);
            #pragma unroll
            for (int t = 0; t < 8; ++t) {
                const int v = __shfl_sync(0xFFFFFFFFu, vidx, src_base + t);
                // ((wx*wy)*wz) multiply order matches reference prod(axis=2).
                const float w = ((t & 4) ? fx : gx) *
                                ((t & 2) ? fy : gy) *
                                ((t & 1) ? fz : gz);
                if (v >= 0) {
                    const float4 f = __ldg((const float4*)(fp + (size_t)v * 32));
                    acc.x = fmaf(f.x, w, acc.x);
                    acc.y = fmaf(f.y, w, acc.y);
                    acc.z = fmaf(f.z, w, acc.z);
                    acc.w = fmaf(f.w, w, acc.w);
                }
            }
            if (qi < M) {
                *(float4*)(out + (size_t)qi * 64 + level * 32 + s * 4) = acc;
            }
        }

        if (!has_next) break;
        p = pn; qi = qin; fx = fxn; fy = fyn; fz = fzn; vidx = vidxn;
    }
}

extern "C" void kernel_launch(void* const* d_in, const int* in_sizes, int n_in,
                              void* d_out, int out_size)
{
    const float* q  = (const float*)d_in[0];
    const float* f0 = (const float*)d_in[1];
    const float* f1 = (const float*)d_in[2];
    const int*   h0 = (const int*)d_in[3];
    const int*   h1 = (const int*)d_in[4];
    float* out = (float*)d_out;

    const int M = in_sizes[0] / 3;
    const int npairs = (M + 1) / 2;

    // Persistent-style sizing: fill the chip (148 SMs x 6 blocks of 256).
    int blocks = 148 * 6;
    const int max_blocks = (npairs + 7) / 8;   // 8 warps per block
    if (blocks > max_blocks) blocks = max_blocks;

    voxel_hash_kernel<<<blocks, 256>>>(q, f0, f1, h0, h1, out, M);
}

// round 12
// speedup vs baseline: 1.1987x; 1.1987x over previous
#include <cuda_runtime.h>
#include <cstdint>

// VoxelHashTable: 2-level hash-grid trilinear interpolation.
// Inputs (metadata order):
//   d_in[0] query_pts (M,3) f32
//   d_in[1] feats0    (n0,32) f32
//   d_in[2] feats1    (n1,32) f32
//   d_in[3] h2v0      (2^20) i32
//   d_in[4] h2v1      (2^20) i32
// Output: (M, 64) f32  — [level0 32 | level1 32]
//
// Warp layout (1 warp = 8 queries = 4 pairs). Per-pair lane roles:
//   half  = lane>>4        which query of the pair
//   level = (lane>>3)&1    resolution level this lane serves
//   s     = lane&7         channel chunk (floats 4s..4s+3)
// Structure (scaled-up R7, the proven best shape): straight-line prologue
// computes all 4 pairs and issues all 4 scattered hash LDGs back-to-back
// (4 independent loads in flight at the chain head), then 4 SEQUENTIAL
// gathers — ptxas pipelines within each gather; manual interleaving and
// grid-stride pipelining both regressed.
// __launch_bounds__(256, 5): 48-reg budget for the 4-pair carry
// ((256,6)=40 would spill it; (256,7)=32 spilled even 2 pairs).

#define TSIZE_MASK ((1 << 20) - 1)

// PRIMES % 2^20 (exact):
#define PMX 455773
#define PMY 475301
#define PMZ 655287

__global__ __launch_bounds__(256, 5) void voxel_hash_kernel(
    const float* __restrict__ q,
    const float* __restrict__ f0,
    const float* __restrict__ f1,
    const int* __restrict__ h0,
    const int* __restrict__ h1,
    float* __restrict__ out,
    int M)
{
    const int wid  = (blockIdx.x * blockDim.x + threadIdx.x) >> 5;
    const int lane = threadIdx.x & 31;

    const int level = (lane >> 3) & 1;
    const int s     = lane & 7;
    const int half  = lane >> 4;

    const float res = level ? 0.24f : 0.12f;   // 0.24f == float32(0.12*2.0)
    const int*   __restrict__ hp = level ? h1 : h0;
    const float* __restrict__ fp = (level ? f1 : f0) + s * 4;
    const int src_base = lane & 0x18;          // (half<<4) | (level<<3)
    const int oxb = (lane >> 2) & 1;
    const int oyb = (lane >> 1) & 1;
    const int ozb = lane & 1;

    const int base = wid * 8;                  // 8 queries per warp

    int   qi[4];
    float fx[4], fy[4], fz[4];
    int   vidx[4];

    // ---- Prologue: 4 pairs' query points + 4 hash LDGs in flight ----
    #pragma unroll
    for (int p = 0; p < 4; ++p) {
        int qq = base + p * 2 + half;
        if (qq >= M) qq = M - 1;               // clamp; store guarded below
        qi[p] = qq;

        const float px = __ldg(q + qq * 3 + 0);
        const float py = __ldg(q + qq * 3 + 1);
        const float pz = __ldg(q + qq * 3 + 2);

        const float sx = __fdiv_rn(px, res);
        const float sy = __fdiv_rn(py, res);
        const float sz = __fdiv_rn(pz, res);
        const float bx = floorf(sx), by = floorf(sy), bz = floorf(sz);
        fx[p] = sx - bx; fy[p] = sy - by; fz[p] = sz - bz;

        const unsigned hv = ((unsigned)(((int)bx + oxb) * PMX +
                                        ((int)by + oyb) * PMY +
                                        ((int)bz + ozb) * PMZ)) & TSIZE_MASK;
        vidx[p] = __ldg(hp + hv);
    }

    // ---- 4 sequential gathers ----
    #pragma unroll
    for (int p = 0; p < 4; ++p) {
        const float lfx = fx[p], lfy = fy[p], lfz = fz[p];
        const float gx = 1.0f - lfx, gy = 1.0f - lfy, gz = 1.0f - lfz;
        float4 acc = make_float4(0.f, 0.f, 0.f, 0.f);

        #pragma unroll
        for (int t = 0; t < 8; ++t) {
            const int v = __shfl_sync(0xFFFFFFFFu, vidx[p], src_base + t);
            // ((wx*wy)*wz) multiply order matches reference prod(axis=2).
            const float w = ((t & 4) ? lfx : gx) *
                            ((t & 2) ? lfy : gy) *
                            ((t & 1) ? lfz : gz);
            if (v >= 0) {
                const float4 f = __ldg((const float4*)(fp + (size_t)v * 32));
                acc.x = fmaf(f.x, w, acc.x);
                acc.y = fmaf(f.y, w, acc.y);
                acc.z = fmaf(f.z, w, acc.z);
                acc.w = fmaf(f.w, w, acc.w);
            }
        }

        const int qq = base + p * 2 + half;
        if (qq < M) {
            *(float4*)(out + (size_t)qi[p] * 64 + level * 32 + s * 4) = acc;
        }
    }
}

extern "C" void kernel_launch(void* const* d_in, const int* in_sizes, int n_in,
                              void* d_out, int out_size)
{
    const float* q  = (const float*)d_in[0];
    const float* f0 = (const float*)d_in[1];
    const float* f1 = (const float*)d_in[2];
    const int*   h0 = (const int*)d_in[3];
    const int*   h1 = (const int*)d_in[4];
    float* out = (float*)d_out;

    const int M = in_sizes[0] / 3;
    const int warps = (M + 7) / 8;          // 8 queries per warp

    const int warps_per_block = 8;
    const int blocks = (warps + warps_per_block - 1) / warps_per_block;
    voxel_hash_kernel<<<blocks, warps_per_block * 32>>>(q, f0, f1, h0, h1, out, M);
}